// round 12
// baseline (speedup 1.0000x reference)
#include <cuda_runtime.h>
#include <cmath>

#define NLEVELS 16
#define TBL 524288u          /* hashmap size, power of 2 */
#define BLOCK 256
/* level-0 corner indices reach up to 16 + 16*16 + 16*256 = 4368 (reference
   aliases into level 1's region); stage 4608 entries to cover it. */
#define L0_STAGE 4608        /* float2 entries staged = 36 KB */

struct LevelParams {
    float    scale[NLEVELS];
    unsigned res[NLEVELS];
    unsigned off[NLEVELS];   /* offset into latents, in float2 entries */
    int      fhl;            /* first hash level */
};

/* compute the 8 corner indices (ABSOLUTE, offset folded in) + fractional coords */
__device__ __forceinline__ void calc_level(const LevelParams& lp, int l,
                                           float px, float py, float pz,
                                           unsigned idx[8],
                                           float& rx, float& ry, float& rz)
{
    const float s = lp.scale[l];
    /* match reference: separate mul then add (no fma contraction) */
    const float sx = __fadd_rn(__fmul_rn(px, s), 0.5f);
    const float sy = __fadd_rn(__fmul_rn(py, s), 0.5f);
    const float sz = __fadd_rn(__fmul_rn(pz, s), 0.5f);
    const float fx = floorf(sx), fy = floorf(sy), fz = floorf(sz);
    rx = sx - fx; ry = sy - fy; rz = sz - fz;
    const unsigned x0 = (unsigned)fx;
    const unsigned y0 = (unsigned)fy;
    const unsigned z0 = (unsigned)fz;
    const unsigned off = lp.off[l];

    /* corner c = (i<<2) | (j<<1) | k  (CELL_OFFSETS loop order i,j,k = x,y,z) */
    if (l < lp.fhl) {
        const unsigned r  = lp.res[l];
        const unsigned r2 = r * r;
        const unsigned base = off + x0 + y0 * r + z0 * r2;  /* strides [1, r, r^2] */
        idx[0] = base;           idx[1] = base + r2;
        idx[2] = base + r;       idx[3] = base + r + r2;
        idx[4] = base + 1u;      idx[5] = base + 1u + r2;
        idx[6] = base + 1u + r;  idx[7] = base + 1u + r + r2;
    } else {
        const unsigned hy0 = y0 * 2654435761u;
        const unsigned hy1 = hy0 + 2654435761u;   /* (y0+1)*p1, mod 2^32 */
        const unsigned hz0 = z0 * 805459861u;
        const unsigned hz1 = hz0 + 805459861u;
        const unsigned m = TBL - 1u;
        const unsigned x1 = x0 + 1u;
        idx[0] = off + ((x0 ^ hy0 ^ hz0) & m);
        idx[1] = off + ((x0 ^ hy0 ^ hz1) & m);
        idx[2] = off + ((x0 ^ hy1 ^ hz0) & m);
        idx[3] = off + ((x0 ^ hy1 ^ hz1) & m);
        idx[4] = off + ((x1 ^ hy0 ^ hz0) & m);
        idx[5] = off + ((x1 ^ hy0 ^ hz1) & m);
        idx[6] = off + ((x1 ^ hy1 ^ hz0) & m);
        idx[7] = off + ((x1 ^ hy1 ^ hz1) & m);
    }
}

/* issue the 8 gathers for one level from ABSOLUTE indices; merge corner pairs
   (c, c+4) into one float4 load when the absolute pair is {2k, 2k+1} — which
   also guarantees 16B alignment (latents base is >=256B aligned). */
__device__ __forceinline__ void load_level(const float2* __restrict__ lat,
                                           const unsigned idx[8], float2 v[8])
{
#pragma unroll
    for (int k = 0; k < 4; ++k) {
        const unsigned a = idx[k];
        const unsigned b = idx[k + 4];
        if ((a ^ b) == 1u) {
            const float4 q = __ldg(reinterpret_cast<const float4*>(lat) + (a >> 1));
            const float2 lo = make_float2(q.x, q.y);
            const float2 hi = make_float2(q.z, q.w);
            if (a & 1u) { v[k] = hi; v[k + 4] = lo; }
            else        { v[k] = lo; v[k + 4] = hi; }
        } else {
            v[k]     = __ldg(lat + a);
            v[k + 4] = __ldg(lat + b);
        }
    }
}

/* trilinear reduce + transpose-buffer store for one level */
__device__ __forceinline__ void reduce_store(float* s_out, int tid, int l,
                                             float rx, float ry, float rz,
                                             const float2 vv[8])
{
    const float wx0 = 1.0f - rx, wx1 = rx;
    const float wy0 = 1.0f - ry, wy1 = ry;
    const float wz0 = 1.0f - rz, wz1 = rz;
    const float w00 = wx0 * wy0, w01 = wx0 * wy1;
    const float w10 = wx1 * wy0, w11 = wx1 * wy1;
    const float w0 = w00 * wz0, w1 = w00 * wz1;
    const float w2 = w01 * wz0, w3 = w01 * wz1;
    const float w4 = w10 * wz0, w5 = w10 * wz1;
    const float w6 = w11 * wz0, w7 = w11 * wz1;

    float a = w0 * vv[0].x + w1 * vv[1].x + w2 * vv[2].x + w3 * vv[3].x
            + w4 * vv[4].x + w5 * vv[5].x + w6 * vv[6].x + w7 * vv[7].x;
    float b = w0 * vv[0].y + w1 * vv[1].y + w2 * vv[2].y + w3 * vv[3].y
            + w4 * vv[4].y + w5 * vv[5].y + w6 * vv[6].y + w7 * vv[7].y;

    s_out[(2 * l + 0) * 257 + tid] = a;
    s_out[(2 * l + 1) * 257 + tid] = b;
}

__global__ __launch_bounds__(BLOCK, 3)
void hashgrid_enc_kernel(const float* __restrict__ pos,
                         const float* __restrict__ latents,
                         float* __restrict__ out,
                         int n_points, LevelParams lp)
{
    /* dynamic smem: [0, 2*L0_STAGE) floats = staged level-0(+spill) table,
                     then 32*257 floats = output transpose buffer */
    extern __shared__ float smem[];
    float2* s_table = reinterpret_cast<float2*>(smem);
    float*  s_out   = smem + 2 * L0_STAGE;

    const int tid = threadIdx.x;
    const int p   = blockIdx.x * BLOCK + tid;
    const int pc  = (p < n_points) ? p : (n_points > 0 ? n_points - 1 : 0);

    const float px = pos[pc * 3 + 0];
    const float py = pos[pc * 3 + 1];
    const float pz = pos[pc * 3 + 2];

    const float2* __restrict__ lat = (const float2*)latents;

    /* depth-2 pipeline over levels 1..15 (identical body to the 86.4us kernel);
       level 0 is peeled out and served from shared memory in the epilogue. */
    float2 v[2][8];
    float  fr[2][3];

    {
        unsigned idx[8];
        calc_level(lp, 1, px, py, pz, idx, fr[1][0], fr[1][1], fr[1][2]);
        load_level(lat, idx, v[1]);
    }

    /* stage first L0_STAGE entries (2304 float4, 9/thread, coalesced) while the
       level-1 gathers are in flight */
    {
        const float4* tsrc = reinterpret_cast<const float4*>(latents);
        float4*       tdst = reinterpret_cast<float4*>(s_table);
#pragma unroll
        for (int i = 0; i < (L0_STAGE / 2) / BLOCK; ++i)
            tdst[i * BLOCK + tid] = __ldg(tsrc + i * BLOCK + tid);
    }
    __syncthreads();

#pragma unroll
    for (int l = 1; l < NLEVELS; ++l) {
        const int cur = l & 1;
        const int nxt = cur ^ 1;
        if (l + 1 < NLEVELS) {
            unsigned idx[8];
            calc_level(lp, l + 1, px, py, pz, idx, fr[nxt][0], fr[nxt][1], fr[nxt][2]);
            load_level(lat, idx, v[nxt]);
        }
        reduce_store(s_out, tid, l, fr[cur][0], fr[cur][1], fr[cur][2], v[cur]);
    }

    /* epilogue: level 0 from shared memory (absolute indices; off[0]==0; max
       reachable index 4368 < L0_STAGE, matching the reference's aliasing) */
    {
        unsigned id0[8];
        float rx, ry, rz;
        calc_level(lp, 0, px, py, pz, id0, rx, ry, rz);
        float2 vv[8];
#pragma unroll
        for (int k = 0; k < 8; ++k) vv[k] = s_table[id0[k]];
        reduce_store(s_out, tid, 0, rx, ry, rz, vv);
    }

    __syncthreads();

    /* coalesced streaming store */
    const int blockBase = blockIdx.x * (BLOCK * 32);
#pragma unroll
    for (int i = 0; i < 8; ++i) {
        const int g4 = i * BLOCK + tid;    /* float4 index within block */
        const int g  = g4 * 4;
        const int pl = g >> 5;             /* point-in-block */
        const int c  = g & 31;             /* feature column */
        float4 vs;
        vs.x = s_out[(c + 0) * 257 + pl];
        vs.y = s_out[(c + 1) * 257 + pl];
        vs.z = s_out[(c + 2) * 257 + pl];
        vs.w = s_out[(c + 3) * 257 + pl];
        if (blockBase + g < n_points * 32)
            __stwt(reinterpret_cast<float4*>(out + blockBase + g), vs);
    }
}

static void fill_level_params(LevelParams& lp)
{
    /* mirror reference _level_params() in double precision */
    const double b = exp((log(2048.0) - log(16.0)) / 15.0);
    unsigned off = 0;
    int fhl = 0;
    for (int i = 0; i < NLEVELS; ++i) {
        const double scale = 16.0 * pow(b, (double)i) - 1.0;
        lp.scale[i] = (float)scale;
        const unsigned res = (unsigned)ceil(scale) + 1u;
        lp.res[i] = res;
        unsigned long long n = (unsigned long long)res * res * res;
        lp.off[i] = off;
        if (n <= (unsigned long long)TBL) { fhl += 1; off += (unsigned)n; }
        else                              { off += TBL; }
    }
    lp.fhl = fhl;
}

extern "C" void kernel_launch(void* const* d_in, const int* in_sizes, int n_in,
                              void* d_out, int out_size)
{
    const float* pos     = (const float*)d_in[0];
    const float* latents = (const float*)d_in[1];
    float*       out     = (float*)d_out;

    const int n_points = in_sizes[0] / 3;

    LevelParams lp;
    fill_level_params(lp);

    const int smem_bytes = (2 * L0_STAGE + 32 * 257) * (int)sizeof(float);
    cudaFuncSetAttribute(hashgrid_enc_kernel,
                         cudaFuncAttributeMaxDynamicSharedMemorySize, smem_bytes);

    const int blocks = (n_points + BLOCK - 1) / BLOCK;
    hashgrid_enc_kernel<<<blocks, BLOCK, smem_bytes>>>(pos, latents, out, n_points, lp);
}

// round 13
// speedup vs baseline: 1.9685x; 1.9685x over previous
#include <cuda_runtime.h>
#include <cmath>

#define NLEVELS 16
#define TBL 524288u          /* hashmap size, power of 2 */
#define BLOCK 256

struct LevelParams {
    float    scale[NLEVELS];
    unsigned res[NLEVELS];
    unsigned off[NLEVELS];   /* offset into latents, in float2 entries */
    int      fhl;            /* first hash level */
};

/* compute the 8 corner indices (ABSOLUTE, offset folded in) + fractional coords */
__device__ __forceinline__ void calc_level(const LevelParams& lp, int l,
                                           float px, float py, float pz,
                                           unsigned idx[8],
                                           float& rx, float& ry, float& rz)
{
    const float s = lp.scale[l];
    /* match reference: separate mul then add (no fma contraction) */
    const float sx = __fadd_rn(__fmul_rn(px, s), 0.5f);
    const float sy = __fadd_rn(__fmul_rn(py, s), 0.5f);
    const float sz = __fadd_rn(__fmul_rn(pz, s), 0.5f);
    const float fx = floorf(sx), fy = floorf(sy), fz = floorf(sz);
    rx = sx - fx; ry = sy - fy; rz = sz - fz;
    const unsigned x0 = (unsigned)fx;
    const unsigned y0 = (unsigned)fy;
    const unsigned z0 = (unsigned)fz;
    const unsigned off = lp.off[l];

    /* corner c = (i<<2) | (j<<1) | k  (CELL_OFFSETS loop order i,j,k = x,y,z) */
    if (l < lp.fhl) {
        const unsigned r  = lp.res[l];
        const unsigned r2 = r * r;
        const unsigned base = off + x0 + y0 * r + z0 * r2;  /* strides [1, r, r^2] */
        idx[0] = base;           idx[1] = base + r2;
        idx[2] = base + r;       idx[3] = base + r + r2;
        idx[4] = base + 1u;      idx[5] = base + 1u + r2;
        idx[6] = base + 1u + r;  idx[7] = base + 1u + r + r2;
    } else {
        const unsigned hy0 = y0 * 2654435761u;
        const unsigned hy1 = hy0 + 2654435761u;   /* (y0+1)*p1, mod 2^32 */
        const unsigned hz0 = z0 * 805459861u;
        const unsigned hz1 = hz0 + 805459861u;
        const unsigned m = TBL - 1u;
        const unsigned x1 = x0 + 1u;
        idx[0] = off + ((x0 ^ hy0 ^ hz0) & m);
        idx[1] = off + ((x0 ^ hy0 ^ hz1) & m);
        idx[2] = off + ((x0 ^ hy1 ^ hz0) & m);
        idx[3] = off + ((x0 ^ hy1 ^ hz1) & m);
        idx[4] = off + ((x1 ^ hy0 ^ hz0) & m);
        idx[5] = off + ((x1 ^ hy0 ^ hz1) & m);
        idx[6] = off + ((x1 ^ hy1 ^ hz0) & m);
        idx[7] = off + ((x1 ^ hy1 ^ hz1) & m);
    }
}

/* issue the 8 gathers for one level from ABSOLUTE indices; merge corner pairs
   (c, c+4) into one float4 load when the absolute pair is {2k, 2k+1} — which
   also guarantees 16B alignment (latents base is >=256B aligned). */
__device__ __forceinline__ void load_level(const float2* __restrict__ lat,
                                           const unsigned idx[8], float2 v[8])
{
#pragma unroll
    for (int k = 0; k < 4; ++k) {
        const unsigned a = idx[k];
        const unsigned b = idx[k + 4];
        if ((a ^ b) == 1u) {
            const float4 q = __ldg(reinterpret_cast<const float4*>(lat) + (a >> 1));
            const float2 lo = make_float2(q.x, q.y);
            const float2 hi = make_float2(q.z, q.w);
            if (a & 1u) { v[k] = hi; v[k + 4] = lo; }
            else        { v[k] = lo; v[k + 4] = hi; }
        } else {
            v[k]     = __ldg(lat + a);
            v[k + 4] = __ldg(lat + b);
        }
    }
}

__global__ __launch_bounds__(BLOCK, 3)
void hashgrid_enc_kernel(const float* __restrict__ pos,
                         const float* __restrict__ latents,
                         float* __restrict__ out,
                         int n_points, LevelParams lp)
{
    /* columns = 32 output features, rows = 256 points, pad 257 for bank-conflict-free
       transpose. */
    __shared__ float s_out[32 * 257];

    const int tid = threadIdx.x;
    const int p   = blockIdx.x * BLOCK + tid;
    const int pc  = (p < n_points) ? p : (n_points > 0 ? n_points - 1 : 0);

    const float px = pos[pc * 3 + 0];
    const float py = pos[pc * 3 + 1];
    const float pz = pos[pc * 3 + 2];

    const float2* __restrict__ lat = (const float2*)latents;

    /* two-deep software pipeline: level l+1's gathers are in flight while
       level l is being reduced. */
    float2 v[2][8];
    float  fr[2][3];

    {
        unsigned idx[8];
        calc_level(lp, 0, px, py, pz, idx, fr[0][0], fr[0][1], fr[0][2]);
        load_level(lat, idx, v[0]);
    }

#pragma unroll
    for (int l = 0; l < NLEVELS; ++l) {
        const int cur = l & 1;
        const int nxt = cur ^ 1;
        if (l + 1 < NLEVELS) {
            unsigned idx[8];
            calc_level(lp, l + 1, px, py, pz, idx, fr[nxt][0], fr[nxt][1], fr[nxt][2]);
            load_level(lat, idx, v[nxt]);
        }

        const float rx = fr[cur][0], ry = fr[cur][1], rz = fr[cur][2];
        const float wx0 = 1.0f - rx, wx1 = rx;
        const float wy0 = 1.0f - ry, wy1 = ry;
        const float wz0 = 1.0f - rz, wz1 = rz;
        const float w00 = wx0 * wy0, w01 = wx0 * wy1;
        const float w10 = wx1 * wy0, w11 = wx1 * wy1;
        const float w0 = w00 * wz0, w1 = w00 * wz1;
        const float w2 = w01 * wz0, w3 = w01 * wz1;
        const float w4 = w10 * wz0, w5 = w10 * wz1;
        const float w6 = w11 * wz0, w7 = w11 * wz1;

        const float2* vv = v[cur];
        float a = w0 * vv[0].x + w1 * vv[1].x + w2 * vv[2].x + w3 * vv[3].x
                + w4 * vv[4].x + w5 * vv[5].x + w6 * vv[6].x + w7 * vv[7].x;
        float b = w0 * vv[0].y + w1 * vv[1].y + w2 * vv[2].y + w3 * vv[3].y
                + w4 * vv[4].y + w5 * vv[5].y + w6 * vv[6].y + w7 * vv[7].y;

        s_out[(2 * l + 0) * 257 + tid] = a;
        s_out[(2 * l + 1) * 257 + tid] = b;
    }

    __syncthreads();

    /* coalesced store, streaming (write-through) so the 33.5 MB output stream
       does not evict the latent table from L2 */
    const int blockBase = blockIdx.x * (BLOCK * 32);
#pragma unroll
    for (int i = 0; i < 8; ++i) {
        const int g4 = i * BLOCK + tid;    /* float4 index within block */
        const int g  = g4 * 4;
        const int pl = g >> 5;             /* point-in-block */
        const int c  = g & 31;             /* feature column */
        float4 vs;
        vs.x = s_out[(c + 0) * 257 + pl];
        vs.y = s_out[(c + 1) * 257 + pl];
        vs.z = s_out[(c + 2) * 257 + pl];
        vs.w = s_out[(c + 3) * 257 + pl];
        if (blockBase + g < n_points * 32)
            __stwt(reinterpret_cast<float4*>(out + blockBase + g), vs);
    }
}

static void fill_level_params(LevelParams& lp)
{
    /* mirror reference _level_params() in double precision */
    const double b = exp((log(2048.0) - log(16.0)) / 15.0);
    unsigned off = 0;
    int fhl = 0;
    for (int i = 0; i < NLEVELS; ++i) {
        const double scale = 16.0 * pow(b, (double)i) - 1.0;
        lp.scale[i] = (float)scale;
        const unsigned res = (unsigned)ceil(scale) + 1u;
        lp.res[i] = res;
        unsigned long long n = (unsigned long long)res * res * res;
        lp.off[i] = off;
        if (n <= (unsigned long long)TBL) { fhl += 1; off += (unsigned)n; }
        else                              { off += TBL; }
    }
    lp.fhl = fhl;
}

extern "C" void kernel_launch(void* const* d_in, const int* in_sizes, int n_in,
                              void* d_out, int out_size)
{
    const float* pos     = (const float*)d_in[0];
    const float* latents = (const float*)d_in[1];
    float*       out     = (float*)d_out;

    const int n_points = in_sizes[0] / 3;

    LevelParams lp;
    fill_level_params(lp);

    const int blocks = (n_points + BLOCK - 1) / BLOCK;
    hashgrid_enc_kernel<<<blocks, BLOCK>>>(pos, latents, out, n_points, lp);
}

// round 14
// speedup vs baseline: 1.9729x; 1.0022x over previous
#include <cuda_runtime.h>
#include <cmath>

#define NLEVELS 16
#define TBL 524288u          /* hashmap size, power of 2 */
#define BLOCK 256            /* threads; 128 points per block (2 threads/point) */
#define PTS   128

struct LevelParams {
    float    scale[NLEVELS];
    unsigned res[NLEVELS];
    unsigned off[NLEVELS];   /* offset into latents, in float2 entries */
    int      fhl;            /* first hash level */
};

/* 4 corner indices for this thread's y-half (ABSOLUTE, offset folded in).
   Corner slots: v[0]=(x0,z0) v[1]=(x0,z1) v[2]=(x1,z0) v[3]=(x1,z1);
   x-merge pairs are (0,2) and (1,3). */
__device__ __forceinline__ void calc_level_half(const LevelParams& lp, int l, int half,
                                                float px, float py, float pz,
                                                unsigned idx[4],
                                                float& rx, float& ry, float& rz)
{
    const float s = lp.scale[l];
    /* match reference: separate mul then add (no fma contraction) */
    const float sx = __fadd_rn(__fmul_rn(px, s), 0.5f);
    const float sy = __fadd_rn(__fmul_rn(py, s), 0.5f);
    const float sz = __fadd_rn(__fmul_rn(pz, s), 0.5f);
    const float fx = floorf(sx), fy = floorf(sy), fz = floorf(sz);
    rx = sx - fx; ry = sy - fy; rz = sz - fz;
    const unsigned x0 = (unsigned)fx;
    const unsigned yh = (unsigned)fy + (unsigned)half;
    const unsigned z0 = (unsigned)fz;
    const unsigned off = lp.off[l];

    if (l < lp.fhl) {
        const unsigned r  = lp.res[l];
        const unsigned r2 = r * r;
        const unsigned base = off + x0 + yh * r + z0 * r2;  /* strides [1, r, r^2] */
        idx[0] = base;
        idx[1] = base + r2;
        idx[2] = base + 1u;
        idx[3] = base + 1u + r2;
    } else {
        const unsigned hy  = yh * 2654435761u;
        const unsigned hz0 = z0 * 805459861u;
        const unsigned hz1 = hz0 + 805459861u;
        const unsigned m = TBL - 1u;
        const unsigned x1 = x0 + 1u;
        idx[0] = off + ((x0 ^ hy ^ hz0) & m);
        idx[1] = off + ((x0 ^ hy ^ hz1) & m);
        idx[2] = off + ((x1 ^ hy ^ hz0) & m);
        idx[3] = off + ((x1 ^ hy ^ hz1) & m);
    }
}

/* 4 gathers (2 x-pairs); merge a pair into one aligned float4 when the absolute
   indices are {2k, 2k+1} (guarantees 16B alignment; latents base >=256B aligned). */
__device__ __forceinline__ void load_level_half(const float2* __restrict__ lat,
                                                const unsigned idx[4], float2 v[4])
{
#pragma unroll
    for (int k = 0; k < 2; ++k) {
        const unsigned a = idx[k];
        const unsigned b = idx[k + 2];
        if ((a ^ b) == 1u) {
            const float4 q = __ldg(reinterpret_cast<const float4*>(lat) + (a >> 1));
            const float2 lo = make_float2(q.x, q.y);
            const float2 hi = make_float2(q.z, q.w);
            if (a & 1u) { v[k] = hi; v[k + 2] = lo; }
            else        { v[k] = lo; v[k + 2] = hi; }
        } else {
            v[k]     = __ldg(lat + a);
            v[k + 2] = __ldg(lat + b);
        }
    }
}

__global__ __launch_bounds__(BLOCK, 4)
void hashgrid_enc_kernel(const float* __restrict__ pos,
                         const float* __restrict__ latents,
                         float* __restrict__ out,
                         int n_points, LevelParams lp)
{
    /* 32 feature rows x 128 points, pad 129 for conflict-free transpose */
    __shared__ float s_out[32 * 129];

    const int tid  = threadIdx.x;
    const int half = tid & 1;            /* y-corner half this thread owns */
    const int pl   = tid >> 1;           /* point-in-block 0..127 */
    const int p    = blockIdx.x * PTS + pl;
    const int pc   = (p < n_points) ? p : (n_points > 0 ? n_points - 1 : 0);

    const float px = pos[pc * 3 + 0];
    const float py = pos[pc * 3 + 1];
    const float pz = pos[pc * 3 + 2];

    const float2* __restrict__ lat = (const float2*)latents;

    /* two-deep software pipeline, halved per-thread state */
    float2 v[2][4];
    float  fr[2][3];

    {
        unsigned idx[4];
        calc_level_half(lp, 0, half, px, py, pz, idx, fr[0][0], fr[0][1], fr[0][2]);
        load_level_half(lat, idx, v[0]);
    }

#pragma unroll
    for (int l = 0; l < NLEVELS; ++l) {
        const int cur = l & 1;
        const int nxt = cur ^ 1;
        if (l + 1 < NLEVELS) {
            unsigned idx[4];
            calc_level_half(lp, l + 1, half, px, py, pz, idx,
                            fr[nxt][0], fr[nxt][1], fr[nxt][2]);
            load_level_half(lat, idx, v[nxt]);
        }

        const float rx = fr[cur][0], ry = fr[cur][1], rz = fr[cur][2];
        const float wy = half ? ry : (1.0f - ry);
        const float wx0 = (1.0f - rx) * wy, wx1 = rx * wy;
        const float wz0 = 1.0f - rz,        wz1 = rz;
        const float w0 = wx0 * wz0, w1 = wx0 * wz1;
        const float w2 = wx1 * wz0, w3 = wx1 * wz1;

        const float2* vv = v[cur];
        float a = w0 * vv[0].x + w1 * vv[1].x + w2 * vv[2].x + w3 * vv[3].x;
        float b = w0 * vv[0].y + w1 * vv[1].y + w2 * vv[2].y + w3 * vv[3].y;

        /* combine the two y-halves within the lane pair */
        a += __shfl_xor_sync(0xffffffffu, a, 1);
        b += __shfl_xor_sync(0xffffffffu, b, 1);

        /* even lane stores feature 2l, odd lane feature 2l+1 */
        const int row = 2 * l + half;
        s_out[row * 129 + pl] = half ? b : a;
    }

    __syncthreads();

    /* coalesced streaming store: 128 pts * 32 floats = 1024 float4 per block */
    const int blockBase = blockIdx.x * (PTS * 32);
#pragma unroll
    for (int i = 0; i < 4; ++i) {
        const int g4 = i * BLOCK + tid;    /* float4 index within block */
        const int g  = g4 * 4;
        const int pp = g >> 5;             /* point-in-block */
        const int c  = g & 31;             /* feature column */
        float4 vs;
        vs.x = s_out[(c + 0) * 129 + pp];
        vs.y = s_out[(c + 1) * 129 + pp];
        vs.z = s_out[(c + 2) * 129 + pp];
        vs.w = s_out[(c + 3) * 129 + pp];
        if (blockBase + g < n_points * 32)
            __stwt(reinterpret_cast<float4*>(out + blockBase + g), vs);
    }
}

static void fill_level_params(LevelParams& lp)
{
    /* mirror reference _level_params() in double precision */
    const double b = exp((log(2048.0) - log(16.0)) / 15.0);
    unsigned off = 0;
    int fhl = 0;
    for (int i = 0; i < NLEVELS; ++i) {
        const double scale = 16.0 * pow(b, (double)i) - 1.0;
        lp.scale[i] = (float)scale;
        const unsigned res = (unsigned)ceil(scale) + 1u;
        lp.res[i] = res;
        unsigned long long n = (unsigned long long)res * res * res;
        lp.off[i] = off;
        if (n <= (unsigned long long)TBL) { fhl += 1; off += (unsigned)n; }
        else                              { off += TBL; }
    }
    lp.fhl = fhl;
}

extern "C" void kernel_launch(void* const* d_in, const int* in_sizes, int n_in,
                              void* d_out, int out_size)
{
    const float* pos     = (const float*)d_in[0];
    const float* latents = (const float*)d_in[1];
    float*       out     = (float*)d_out;

    const int n_points = in_sizes[0] / 3;

    LevelParams lp;
    fill_level_params(lp);

    const int blocks = (n_points + PTS - 1) / PTS;
    hashgrid_enc_kernel<<<blocks, BLOCK>>>(pos, latents, out, n_points, lp);
}